// round 14
// baseline (speedup 1.0000x reference)
#include <cuda_runtime.h>
#include <cuda_fp16.h>
#include <cstdint>

#define G_ 10
#define B_ 32768
#define K_ 1024
#define D_ 256

// ==================== static device scratch ====================
__device__ float    g_rownorm[G_ * B_];
__device__ float    g_cbnorm [G_ * K_];
__device__ double   g_part   [G_ * (B_ / 8)];
__device__ uint32_t g_cand   [(size_t)G_ * B_ * 32];               // packed keys
// FP16 fragment-image of codebook only (A image is built in-kernel)
__device__ __half   g_cbH   [(size_t)G_ * 8 * 8 * 4096];            // 5.25 MB

// ==================== helpers ====================
__device__ __forceinline__ void mma_f16(float* c, const uint32_t* a, const uint32_t* b) {
    asm volatile(
        "mma.sync.aligned.m16n8k16.row.col.f32.f16.f16.f32 "
        "{%0,%1,%2,%3}, {%4,%5,%6,%7}, {%8,%9}, {%0,%1,%2,%3};"
        : "+f"(c[0]), "+f"(c[1]), "+f"(c[2]), "+f"(c[3])
        : "r"(a[0]), "r"(a[1]), "r"(a[2]), "r"(a[3]), "r"(b[0]), "r"(b[1]));
}
__device__ __forceinline__ uint32_t smem_u32(const void* p) {
    uint32_t a;
    asm("{ .reg .u64 t; cvta.to.shared.u64 t, %1; cvt.u32.u64 %0, t; }" : "=r"(a) : "l"(p));
    return a;
}
__device__ __forceinline__ void cp16(uint32_t dst, const void* src) {
    asm volatile("cp.async.cg.shared.global [%0], [%1], 16;" :: "r"(dst), "l"(src));
}
#define CP_COMMIT() asm volatile("cp.async.commit_group;" ::: "memory")
#define CP_WAIT1()  asm volatile("cp.async.wait_group 1;" ::: "memory")

// R9-R12-PROVEN order-preserving key on UNBIASED scores (|v| ~ O(1) so the
// 10-bit truncation is ~1e-4 — harmless). The R13 +512 bias made truncation
// 0.0625 > EPS and broke the candidate guarantee; do not bias.
__device__ __forceinline__ uint32_t fkey(float v, int idx) {
    uint32_t b = __float_as_uint(v);
    uint32_t u = (b & 0x80000000u) ? ~b : (b | 0x80000000u);
    return (u & 0xFFFFFC00u) | (uint32_t)idx;
}
__device__ __forceinline__ float unkey(uint32_t key) {
    uint32_t u = key & 0xFFFFFC00u;
    uint32_t b = (u & 0x80000000u) ? (u ^ 0x80000000u) : ~u;
    return __uint_as_float(b);
}

// ==================== prep_cb: B fragment image + fused cbnorm ====================
// B block (R11/R12-validated pairing): p=n>>4, q=(n>>3)&1:
//   off = ks*2048 + p*256 + lane*8 + q*4 + reg*2 + half
__global__ void prep_cb_kernel(const float* __restrict__ cb) {
    __shared__ __align__(16) __half img[4096];
    const int tid = threadIdx.x;
    const int g = blockIdx.y, nt0 = blockIdx.x;
    const int n = tid >> 1, ks = tid & 1;
    const int pP = n >> 4, qQ = (n >> 3) & 1;
    const float* Cb = cb + ((size_t)g * K_ + (nt0 << 7)) * D_;
    const float* C = Cb + (size_t)n * D_;
    __half* dst = g_cbH + (size_t)(g * 8 + nt0) * 8 * 4096;
    for (int c = 0; c < 8; ++c) {
        const float4* p = (const float4*)(C + (c << 5) + (ks << 4));
        float4 t0 = p[0], t1 = p[1], t2 = p[2], t3 = p[3];
        float v[16] = {t0.x,t0.y,t0.z,t0.w, t1.x,t1.y,t1.z,t1.w,
                       t2.x,t2.y,t2.z,t2.w, t3.x,t3.y,t3.z,t3.w};
#pragma unroll
        for (int jj = 0; jj < 16; jj += 2) {
            int lane = ((n & 7) << 2) | ((jj & 7) >> 1);
            int reg  = jj >> 3;
            int off  = ks * 2048 + pP * 256 + lane * 8 + qQ * 4 + reg * 2;
            *(__half2*)(img + off) = __floats2half2_rn(v[jj], v[jj + 1]);
        }
        __syncthreads();
        float4* o = (float4*)(dst + (size_t)c * 4096 + tid * 16);
        const float4* s = (const float4*)(img + tid * 16);
        o[0] = s[0]; o[1] = s[1];
        __syncthreads();
    }
    // ---- fused cbnorm (identical arithmetic to proven cbnorm_kernel) ----
    const int wid = tid >> 5, lane = tid & 31;
    for (int rr = 0; rr < 16; ++rr) {
        int row = (wid << 4) + rr;
        const float4* rp = (const float4*)(Cb + (size_t)row * D_);
        float4 a = rp[lane], b = rp[lane + 32];
        float s = a.x*a.x + a.y*a.y + a.z*a.z + a.w*a.w
                + b.x*b.x + b.y*b.y + b.z*b.z + b.w*b.w;
#pragma unroll
        for (int off = 16; off; off >>= 1) s += __shfl_down_sync(0xffffffffu, s, off);
        if (!lane) g_cbnorm[(size_t)g * K_ + (nt0 << 7) + row] = s;
    }
}

// ==================== phase 1: fp16 GEMM, in-kernel A build + 3-stage B ring ====================
// smem: A resident [8 x 4096 halves = 64 KB] @0 (built in prologue from raw feats),
//       B ring     [3 stages x 8192 halves = 48 KB] @32768 halves.
// 32 iterations of 64 d; per-score top-4 epilogue (R10/R12-proven, unbiased keys).
#define SMEM_GEMM (112 * 1024)

__global__ void __launch_bounds__(256, 2)
vq_f16_kernel(const float* __restrict__ feats) {
    extern __shared__ __half smh[];
    const uint32_t sb = smem_u32(smh);
    const int tid  = threadIdx.x;
    const int wid  = tid >> 5;
    const int lane = tid & 31;
    const int g    = blockIdx.y;
    const int mt0  = blockIdx.x;
    const int mw   = wid >> 1;
    const int nw   = wid & 1;

    const __half* srcB0 = g_cbH + (size_t)g * 8 * 8 * 4096;
    const float*  Fb    = feats + ((size_t)g * B_ + (mt0 << 7)) * D_;

    // ---- start B pipeline first so cp.async overlaps the A build ----
#pragma unroll
    for (int s = 0; s < 2; ++s) {
        uint32_t d = sb + 65536 + s * 16384 + tid * 64;
        const __half* sbp = srcB0 + (size_t)s * 8192 + tid * 32;
        cp16(d, sbp); cp16(d + 16, sbp + 8);
        cp16(d + 32, sbp + 16); cp16(d + 48, sbp + 24);
        CP_COMMIT();
    }

    // ---- build resident A fragment image from raw fp32 feats
    //      (identical layout formulas to the validated prep_feats) ----
    {
        const int srow = tid >> 1, ks = tid & 1;
        const int r = srow & 15, mt = srow >> 4;
        const float* F = Fb + (size_t)srow * D_;
#pragma unroll
        for (int c = 0; c < 8; ++c) {
            const float4* p = (const float4*)(F + (c << 5) + (ks << 4));
            float4 t0 = p[0], t1 = p[1], t2 = p[2], t3 = p[3];
            float v[16] = {t0.x,t0.y,t0.z,t0.w, t1.x,t1.y,t1.z,t1.w,
                           t2.x,t2.y,t2.z,t2.w, t3.x,t3.y,t3.z,t3.w};
#pragma unroll
            for (int jj = 0; jj < 16; jj += 2) {
                int ln = ((r & 7) << 2) | ((jj & 7) >> 1);
                int rg = ((jj >> 3) << 1) | (r >> 3);
                int off = (c << 12) + (ks << 11) + (mt << 8) + (ln << 3) + (rg << 1);
                *(__half2*)(smh + off) = __floats2half2_rn(v[jj], v[jj + 1]);
            }
        }
        // ---- fused rownorm (identical arithmetic to proven rownorm_kernel) ----
        for (int rr = 0; rr < 16; ++rr) {
            int row = (wid << 4) + rr;
            const float4* rp = (const float4*)(Fb + (size_t)row * D_);
            float4 a = rp[lane], b = rp[lane + 32];
            float s = a.x*a.x + a.y*a.y + a.z*a.z + a.w*a.w
                    + b.x*b.x + b.y*b.y + b.z*b.z + b.w*b.w;
#pragma unroll
            for (int off = 16; off; off >>= 1) s += __shfl_down_sync(0xffffffffu, s, off);
            if (!lane) g_rownorm[(size_t)g * B_ + (mt0 << 7) + row] = s;
        }
    }

    uint32_t L[4][4];
#pragma unroll
    for (int l = 0; l < 4; ++l)
#pragma unroll
        for (int s = 0; s < 4; ++s) L[l][s] = 0xFFFFFFFFu;

    float acc[2][8][4];
#pragma unroll
    for (int i = 0; i < 2; ++i)
#pragma unroll
        for (int j = 0; j < 8; ++j)
#pragma unroll
            for (int k = 0; k < 4; ++k) acc[i][j][k] = 0.0f;

    for (int i = 0; i < 32; ++i) {
        CP_WAIT1();
        __syncthreads();   // iter 0: also publishes the A image STS
        const __half* bufBs = smh + 32768 + (i % 3) * 8192;

        // ---- MMA on two 32-d sub-chunks (R11/R12-validated reads) ----
#pragma unroll
        for (int u = 0; u < 2; ++u) {
            const __half* bufA = smh + (((i << 1) + u) & 7) * 4096;
            const __half* bufB = bufBs + (u << 12);
#pragma unroll
            for (int ks = 0; ks < 2; ++ks) {
                uint32_t aF[2][4];
#pragma unroll
                for (int mti = 0; mti < 2; ++mti) {
                    uint4 t = *(const uint4*)(bufA + ks * 2048 + ((mw << 1) + mti) * 256 + lane * 8);
                    aF[mti][0] = t.x; aF[mti][1] = t.y; aF[mti][2] = t.z; aF[mti][3] = t.w;
                }
#pragma unroll
                for (int pp = 0; pp < 4; ++pp) {
                    uint4 bt = *(const uint4*)(bufB + ks * 2048 + ((nw << 2) + pp) * 256 + lane * 8);
                    uint32_t b0[2] = {bt.x, bt.y};
                    uint32_t b1[2] = {bt.z, bt.w};
                    mma_f16(acc[0][(pp << 1)],     aF[0], b0);
                    mma_f16(acc[1][(pp << 1)],     aF[1], b0);
                    mma_f16(acc[0][(pp << 1) + 1], aF[0], b1);
                    mma_f16(acc[1][(pp << 1) + 1], aF[1], b1);
                }
            }
        }

        // ---- refill B stage i+2 ----
        if (i + 2 < 32) {
            const int s = (i + 2) % 3;
            uint32_t d = sb + 65536 + s * 16384 + tid * 64;
            const __half* sbp = srcB0 + (size_t)(i + 2) * 8192 + tid * 32;
            cp16(d, sbp); cp16(d + 16, sbp + 8);
            cp16(d + 32, sbp + 16); cp16(d + 48, sbp + 24);
        }
        CP_COMMIT();

        // ---- epilogue every 4 iters: per-score top-4 insertion
        //      (R10/R12-proven logic, unbiased keys) ----
        if ((i & 3) == 3) {
            const int ntile = i >> 2;
            const float* cnb = g_cbnorm + (size_t)g * K_ + (ntile << 7);
#pragma unroll
            for (int p = 0; p < 4; ++p) {
                int cl0 = (nw << 6) + (p << 4) + ((lane & 3) << 1);
                float2 cnA = __ldg((const float2*)(cnb + cl0));
                float2 cnB = __ldg((const float2*)(cnb + cl0 + 8));
                int gi0 = (ntile << 7) + cl0;
                int gi1 = gi0 + 8;
#pragma unroll
                for (int l = 0; l < 4; ++l) {
                    const int mti = l >> 1, hf = l & 1;
                    float sc[4];
                    int   gi[4];
                    sc[0] = cnA.x - 2.0f * acc[mti][(p << 1)][(hf << 1)];     gi[0] = gi0;
                    sc[1] = cnA.y - 2.0f * acc[mti][(p << 1)][(hf << 1) + 1]; gi[1] = gi0 + 1;
                    sc[2] = cnB.x - 2.0f * acc[mti][(p << 1) + 1][(hf << 1)];     gi[2] = gi1;
                    sc[3] = cnB.y - 2.0f * acc[mti][(p << 1) + 1][(hf << 1) + 1]; gi[3] = gi1 + 1;
#pragma unroll
                    for (int q = 0; q < 4; ++q) {
                        uint32_t k = fkey(sc[q], gi[q]);
                        if (k < L[l][3]) {
                            if (k < L[l][2]) {
                                L[l][3] = L[l][2];
                                if (k < L[l][1]) {
                                    L[l][2] = L[l][1];
                                    if (k < L[l][0]) { L[l][1] = L[l][0]; L[l][0] = k; }
                                    else             { L[l][1] = k; }
                                } else { L[l][2] = k; }
                            } else { L[l][3] = k; }
                        }
                    }
                }
            }
#pragma unroll
            for (int a = 0; a < 2; ++a)
#pragma unroll
                for (int j = 0; j < 8; ++j)
#pragma unroll
                    for (int k = 0; k < 4; ++k) acc[a][j][k] = 0.0f;
        }
    }

    // ---- dump 32 keys per row ----
#pragma unroll
    for (int l = 0; l < 4; ++l) {
        const int mti = l >> 1, hf = l & 1;
        int rloc = (mw << 5) + (mti << 4) + (hf << 3) + (lane >> 2);
        size_t r = (size_t)g * B_ + (mt0 << 7) + rloc;
        int s8 = (nw << 2) | (lane & 3);
#pragma unroll
        for (int s = 0; s < 4; ++s)
            g_cand[r * 32 + s8 * 4 + s] = L[l][s];
    }
}

// ==================== phase 2: exact fp32 rescore + gather + loss (proven) ====================
#define EPS_RESCORE 0.03f

__global__ void rescore_gather_kernel(const float* __restrict__ feats,
                                      const float* __restrict__ cb,
                                      float* __restrict__ out_q,
                                      float* __restrict__ out_idx_f) {
    __shared__ double bs[8];
    const int g = blockIdx.y, w = threadIdx.x >> 5, lane = threadIdx.x & 31;
    const size_t row = (size_t)g * B_ + ((size_t)blockIdx.x << 3) + w;

    uint32_t key = g_cand[row * 32 + lane];
    int   ci = (int)(key & 1023u);
    float cv = unkey(key);

    uint32_t kmin = key;
#pragma unroll
    for (int off = 16; off; off >>= 1)
        kmin = min(kmin, __shfl_xor_sync(0xffffffffu, kmin, off));
    float vminf = unkey(kmin);
    unsigned mask = __ballot_sync(0xffffffffu, cv <= vminf + EPS_RESCORE);

    const float4* f4 = (const float4*)(feats + row * D_);
    int bestI;
    if (__popc(mask) == 1) {
        bestI = (int)(kmin & 1023u);
    } else {
        float4 fa = f4[lane * 2], fb = f4[lane * 2 + 1];
        const float rn = g_rownorm[row];
        float bestV = 3.4e38f;
        bestI = 0x7fffffff;
        unsigned m = mask;
        while (m) {
            int j = __ffs(m) - 1;
            m &= m - 1;
            int idx = __shfl_sync(0xffffffffu, ci, j);
            const float4* c4 = (const float4*)(cb + ((size_t)g * K_ + idx) * D_);
            float4 ca = c4[lane * 2], cbv = c4[lane * 2 + 1];
            float p = fa.x*ca.x + fa.y*ca.y + fa.z*ca.z + fa.w*ca.w
                    + fb.x*cbv.x + fb.y*cbv.y + fb.z*cbv.z + fb.w*cbv.w;
#pragma unroll
            for (int off = 16; off; off >>= 1) p += __shfl_xor_sync(0xffffffffu, p, off);
            float cn = g_cbnorm[(size_t)g * K_ + idx];
            float d2 = (rn + cn) - 2.0f * p;       // reference rounding structure (exact)
            if (d2 < bestV || (d2 == bestV && idx < bestI)) { bestV = d2; bestI = idx; }
        }
    }

    const float4* q4 = (const float4*)(cb + ((size_t)g * K_ + bestI) * D_);
    float4* o4 = (float4*)(out_q + row * D_);
    float sl = 0.0f;
#pragma unroll
    for (int it = 0; it < 2; ++it) {
        int p = lane + (it << 5);
        float4 f = f4[p], q = q4[p], o;
        float t;
        t = q.x - f.x; o.x = f.x + t; sl += t * t;
        t = q.y - f.y; o.y = f.y + t; sl += t * t;
        t = q.z - f.z; o.z = f.z + t; sl += t * t;
        t = q.w - f.w; o.w = f.w + t; sl += t * t;
        o4[p] = o;
    }
    double s = (double)sl;
#pragma unroll
    for (int off = 16; off; off >>= 1) s += __shfl_down_sync(0xffffffffu, s, off);
    if (!lane) {
        bs[w] = s;
        out_idx_f[row] = (float)bestI;
    }
    __syncthreads();
    if (!threadIdx.x) {
        double tot = 0.0;
#pragma unroll
        for (int i = 0; i < 8; i++) tot += bs[i];
        g_part[(size_t)g * (B_ / 8) + blockIdx.x] = tot;
    }
}

// ==================== deterministic loss finalize (proven) ====================
__global__ void finalize_kernel(float* __restrict__ out_loss) {
    __shared__ double sh[256];
    __shared__ float gm[G_];
    int tid = threadIdx.x;
    for (int g = 0; g < G_; ++g) {
        double s = 0.0;
        for (int i = tid; i < B_ / 8; i += 256) s += g_part[(size_t)g * (B_ / 8) + i];
        sh[tid] = s;
        __syncthreads();
        for (int st = 128; st; st >>= 1) {
            if (tid < st) sh[tid] += sh[tid + st];
            __syncthreads();
        }
        if (!tid) gm[g] = (float)(sh[0] / (double)((size_t)B_ * D_));
        __syncthreads();
    }
    if (!tid) {
        const float commit[G_] = {0.5f, 0.5f, 0.4f, 0.4f, 0.4f,
                                  0.4f, 0.8f, 0.8f, 0.8f, 0.8f};
        float total = 0.0f;
        for (int g = 0; g < G_; ++g) {
            float e = gm[g];
            total += e + commit[g] * e;
        }
        *out_loss = total;
    }
}

// ==================== launch ====================
extern "C" void kernel_launch(void* const* d_in, const int* in_sizes, int n_in,
                              void* d_out, int out_size) {
    (void)in_sizes; (void)n_in; (void)out_size;
    const float* feats = (const float*)d_in[0];
    const float* cb    = (const float*)d_in[1];
    float* out      = (float*)d_out;
    float* out_q    = out;
    float* out_loss = out + (size_t)G_ * B_ * D_;
    float* out_idx  = out_loss + 1;

    cudaFuncSetAttribute(vq_f16_kernel, cudaFuncAttributeMaxDynamicSharedMemorySize,
                         SMEM_GEMM);

    dim3 pc(8, G_);
    prep_cb_kernel<<<pc, 256>>>(cb);         // B image + fused cbnorm

    dim3 mg(B_ / 128, G_);
    vq_f16_kernel<<<mg, 256, SMEM_GEMM>>>(feats);   // builds A image + rownorm in-kernel

    dim3 gg(B_ / 8, G_);
    rescore_gather_kernel<<<gg, 256>>>(feats, cb, out_q, out_idx);

    finalize_kernel<<<1, 256>>>(out_loss);
}

// round 16
// speedup vs baseline: 1.1695x; 1.1695x over previous
#include <cuda_runtime.h>
#include <cuda_fp16.h>
#include <cstdint>

#define G_ 10
#define B_ 32768
#define K_ 1024
#define D_ 256

// ==================== static device scratch ====================
__device__ float    g_rownorm[G_ * B_];
__device__ float    g_cbnorm [G_ * K_];
__device__ double   g_part   [G_ * (B_ / 8)];
__device__ float    g_gm     [G_];
__device__ uint32_t g_cand   [(size_t)G_ * B_ * 32];               // packed keys
// FP16 fragment-image copies
__device__ __half   g_featsH[(size_t)G_ * (B_ / 128) * 8 * 4096];   // 168 MB
__device__ __half   g_cbH   [(size_t)G_ * 8 * 8 * 4096];            // 5.25 MB

// ==================== helpers ====================
__device__ __forceinline__ void mma_f16(float* c, const uint32_t* a, const uint32_t* b) {
    asm volatile(
        "mma.sync.aligned.m16n8k16.row.col.f32.f16.f16.f32 "
        "{%0,%1,%2,%3}, {%4,%5,%6,%7}, {%8,%9}, {%0,%1,%2,%3};"
        : "+f"(c[0]), "+f"(c[1]), "+f"(c[2]), "+f"(c[3])
        : "r"(a[0]), "r"(a[1]), "r"(a[2]), "r"(a[3]), "r"(b[0]), "r"(b[1]));
}
__device__ __forceinline__ uint32_t smem_u32(const void* p) {
    uint32_t a;
    asm("{ .reg .u64 t; cvta.to.shared.u64 t, %1; cvt.u32.u64 %0, t; }" : "=r"(a) : "l"(p));
    return a;
}
__device__ __forceinline__ void cp16(uint32_t dst, const void* src) {
    asm volatile("cp.async.cg.shared.global [%0], [%1], 16;" :: "r"(dst), "l"(src));
}
#define CP_COMMIT() asm volatile("cp.async.commit_group;" ::: "memory")
#define CP_WAIT1()  asm volatile("cp.async.wait_group 1;" ::: "memory")

// R9-R12-proven order-preserving key on UNBIASED scores (truncation ~1e-4).
__device__ __forceinline__ uint32_t fkey(float v, int idx) {
    uint32_t b = __float_as_uint(v);
    uint32_t u = (b & 0x80000000u) ? ~b : (b | 0x80000000u);
    return (u & 0xFFFFFC00u) | (uint32_t)idx;
}
__device__ __forceinline__ float unkey(uint32_t key) {
    uint32_t u = key & 0xFFFFFC00u;
    uint32_t b = (u & 0x80000000u) ? (u ^ 0x80000000u) : ~u;
    return __uint_as_float(b);
}

// ==================== prep_cb: B fragment image + fused cbnorm (R14-proven) ====================
// B block (R11/R12-validated pairing): p=n>>4, q=(n>>3)&1:
//   off = ks*2048 + p*256 + lane*8 + q*4 + reg*2 + half
__global__ void prep_cb_kernel(const float* __restrict__ cb) {
    __shared__ __align__(16) __half img[4096];
    const int tid = threadIdx.x;
    const int g = blockIdx.y, nt0 = blockIdx.x;
    const int n = tid >> 1, ks = tid & 1;
    const int pP = n >> 4, qQ = (n >> 3) & 1;
    const float* Cb = cb + ((size_t)g * K_ + (nt0 << 7)) * D_;
    const float* C = Cb + (size_t)n * D_;
    __half* dst = g_cbH + (size_t)(g * 8 + nt0) * 8 * 4096;
    for (int c = 0; c < 8; ++c) {
        const float4* p = (const float4*)(C + (c << 5) + (ks << 4));
        float4 t0 = p[0], t1 = p[1], t2 = p[2], t3 = p[3];
        float v[16] = {t0.x,t0.y,t0.z,t0.w, t1.x,t1.y,t1.z,t1.w,
                       t2.x,t2.y,t2.z,t2.w, t3.x,t3.y,t3.z,t3.w};
#pragma unroll
        for (int jj = 0; jj < 16; jj += 2) {
            int lane = ((n & 7) << 2) | ((jj & 7) >> 1);
            int reg  = jj >> 3;
            int off  = ks * 2048 + pP * 256 + lane * 8 + qQ * 4 + reg * 2;
            *(__half2*)(img + off) = __floats2half2_rn(v[jj], v[jj + 1]);
        }
        __syncthreads();
        float4* o = (float4*)(dst + (size_t)c * 4096 + tid * 16);
        const float4* s = (const float4*)(img + tid * 16);
        o[0] = s[0]; o[1] = s[1];
        __syncthreads();
    }
    // ---- fused cbnorm (identical arithmetic to proven cbnorm_kernel) ----
    const int wid = tid >> 5, lane = tid & 31;
    for (int rr = 0; rr < 16; ++rr) {
        int row = (wid << 4) + rr;
        const float4* rp = (const float4*)(Cb + (size_t)row * D_);
        float4 a = rp[lane], b = rp[lane + 32];
        float s = a.x*a.x + a.y*a.y + a.z*a.z + a.w*a.w
                + b.x*b.x + b.y*b.y + b.z*b.z + b.w*b.w;
#pragma unroll
        for (int off = 16; off; off >>= 1) s += __shfl_down_sync(0xffffffffu, s, off);
        if (!lane) g_cbnorm[(size_t)g * K_ + (nt0 << 7) + row] = s;
    }
}

// ==================== prep_feats: A fragment image + fused rownorm (R12-proven) ====================
// A block: off = ks*2048 + (m>>4)*256 + lane*8 + reg*2 + half
__global__ void prep_feats_kernel(const float* __restrict__ feats) {
    __shared__ __align__(16) __half img[4096];
    const int tid = threadIdx.x;
    const int g = blockIdx.y, mt0 = blockIdx.x;
    const int srow = tid >> 1, ks = tid & 1;
    const int r = srow & 15, mt = srow >> 4;
    const float* Fb = feats + ((size_t)g * B_ + (mt0 << 7)) * D_;
    const float* F = Fb + (size_t)srow * D_;
    __half* dst = g_featsH + (size_t)(g * (B_ / 128) + mt0) * 8 * 4096;
    for (int c = 0; c < 8; ++c) {
        const float4* p = (const float4*)(F + (c << 5) + (ks << 4));
        float4 t0 = p[0], t1 = p[1], t2 = p[2], t3 = p[3];
        float v[16] = {t0.x,t0.y,t0.z,t0.w, t1.x,t1.y,t1.z,t1.w,
                       t2.x,t2.y,t2.z,t2.w, t3.x,t3.y,t3.z,t3.w};
#pragma unroll
        for (int jj = 0; jj < 16; jj += 2) {
            int lane = ((r & 7) << 2) | ((jj & 7) >> 1);
            int reg  = ((jj >> 3) << 1) | (r >> 3);
            int off  = ks * 2048 + mt * 256 + lane * 8 + reg * 2;
            *(__half2*)(img + off) = __floats2half2_rn(v[jj], v[jj + 1]);
        }
        __syncthreads();
        float4* o = (float4*)(dst + (size_t)c * 4096 + tid * 16);
        const float4* s = (const float4*)(img + tid * 16);
        o[0] = s[0]; o[1] = s[1];
        __syncthreads();
    }
    // ---- fused rownorm (identical arithmetic to proven rownorm_kernel) ----
    const int wid = tid >> 5, lane = tid & 31;
    for (int rr = 0; rr < 16; ++rr) {
        int row = (wid << 4) + rr;
        const float4* rp = (const float4*)(Fb + (size_t)row * D_);
        float4 a = rp[lane], b = rp[lane + 32];
        float s = a.x*a.x + a.y*a.y + a.z*a.z + a.w*a.w
                + b.x*b.x + b.y*b.y + b.z*b.z + b.w*b.w;
#pragma unroll
        for (int off = 16; off; off >>= 1) s += __shfl_down_sync(0xffffffffu, s, off);
        if (!lane) g_rownorm[(size_t)g * B_ + (mt0 << 7) + row] = s;
    }
}

// ==================== phase 1: fp16 GEMM (byte-identical R12 core) ====================
// smem: A resident [8 x 4096 halves = 64 KB] @0,
//       B ring     [3 stages x 8192 halves = 48 KB] @32768 halves.
#define SMEM_GEMM (112 * 1024)

__global__ void __launch_bounds__(256, 2)
vq_f16_kernel() {
    extern __shared__ __half smh[];
    const uint32_t sb = smem_u32(smh);
    const int tid  = threadIdx.x;
    const int wid  = tid >> 5;
    const int lane = tid & 31;
    const int g    = blockIdx.y;
    const int mt0  = blockIdx.x;
    const int mw   = wid >> 1;
    const int nw   = wid & 1;

    const __half* srcA0 = g_featsH + (size_t)(g * (B_ / 128) + mt0) * 8 * 4096;
    const __half* srcB0 = g_cbH + (size_t)g * 8 * 8 * 4096;

    uint32_t L[4][4];
#pragma unroll
    for (int l = 0; l < 4; ++l)
#pragma unroll
        for (int s = 0; s < 4; ++s) L[l][s] = 0xFFFFFFFFu;

    float acc[2][8][4];
#pragma unroll
    for (int i = 0; i < 2; ++i)
#pragma unroll
        for (int j = 0; j < 8; ++j)
#pragma unroll
            for (int k = 0; k < 4; ++k) acc[i][j][k] = 0.0f;

    // prologue: resident A (1 group), then B stages 0,1 (1 group each)
#pragma unroll
    for (int c = 0; c < 8; ++c) {
        uint32_t d = sb + c * 8192 + tid * 32;
        const __half* sa = srcA0 + (size_t)c * 4096 + tid * 16;
        cp16(d, sa); cp16(d + 16, sa + 8);
    }
    CP_COMMIT();
#pragma unroll
    for (int s = 0; s < 2; ++s) {
        uint32_t d = sb + 65536 + s * 16384 + tid * 64;
        const __half* sbp = srcB0 + (size_t)s * 8192 + tid * 32;
        cp16(d, sbp); cp16(d + 16, sbp + 8);
        cp16(d + 32, sbp + 16); cp16(d + 48, sbp + 24);
        CP_COMMIT();
    }

    for (int i = 0; i < 32; ++i) {
        CP_WAIT1();
        __syncthreads();
        const __half* bufBs = smh + 32768 + (i % 3) * 8192;

        // ---- MMA on two 32-d sub-chunks (R11/R12-validated reads) ----
#pragma unroll
        for (int u = 0; u < 2; ++u) {
            const __half* bufA = smh + (((i << 1) + u) & 7) * 4096;
            const __half* bufB = bufBs + (u << 12);
#pragma unroll
            for (int ks = 0; ks < 2; ++ks) {
                uint32_t aF[2][4];
#pragma unroll
                for (int mti = 0; mti < 2; ++mti) {
                    uint4 t = *(const uint4*)(bufA + ks * 2048 + ((mw << 1) + mti) * 256 + lane * 8);
                    aF[mti][0] = t.x; aF[mti][1] = t.y; aF[mti][2] = t.z; aF[mti][3] = t.w;
                }
#pragma unroll
                for (int pp = 0; pp < 4; ++pp) {
                    uint4 bt = *(const uint4*)(bufB + ks * 2048 + ((nw << 2) + pp) * 256 + lane * 8);
                    uint32_t b0[2] = {bt.x, bt.y};
                    uint32_t b1[2] = {bt.z, bt.w};
                    mma_f16(acc[0][(pp << 1)],     aF[0], b0);
                    mma_f16(acc[1][(pp << 1)],     aF[1], b0);
                    mma_f16(acc[0][(pp << 1) + 1], aF[0], b1);
                    mma_f16(acc[1][(pp << 1) + 1], aF[1], b1);
                }
            }
        }

        // ---- refill B stage i+2 ----
        if (i + 2 < 32) {
            const int s = (i + 2) % 3;
            uint32_t d = sb + 65536 + s * 16384 + tid * 64;
            const __half* sbp = srcB0 + (size_t)(i + 2) * 8192 + tid * 32;
            cp16(d, sbp); cp16(d + 16, sbp + 8);
            cp16(d + 32, sbp + 16); cp16(d + 48, sbp + 24);
        }
        CP_COMMIT();

        // ---- epilogue every 4 iters: per-score top-4 insertion (R12-proven) ----
        if ((i & 3) == 3) {
            const int ntile = i >> 2;
            const float* cnb = g_cbnorm + (size_t)g * K_ + (ntile << 7);
#pragma unroll
            for (int p = 0; p < 4; ++p) {
                int cl0 = (nw << 6) + (p << 4) + ((lane & 3) << 1);
                float2 cnA = __ldg((const float2*)(cnb + cl0));
                float2 cnB = __ldg((const float2*)(cnb + cl0 + 8));
                int gi0 = (ntile << 7) + cl0;
                int gi1 = gi0 + 8;
#pragma unroll
                for (int l = 0; l < 4; ++l) {
                    const int mti = l >> 1, hf = l & 1;
                    float sc[4];
                    int   gi[4];
                    sc[0] = cnA.x - 2.0f * acc[mti][(p << 1)][(hf << 1)];     gi[0] = gi0;
                    sc[1] = cnA.y - 2.0f * acc[mti][(p << 1)][(hf << 1) + 1]; gi[1] = gi0 + 1;
                    sc[2] = cnB.x - 2.0f * acc[mti][(p << 1) + 1][(hf << 1)];     gi[2] = gi1;
                    sc[3] = cnB.y - 2.0f * acc[mti][(p << 1) + 1][(hf << 1) + 1]; gi[3] = gi1 + 1;
#pragma unroll
                    for (int q = 0; q < 4; ++q) {
                        uint32_t k = fkey(sc[q], gi[q]);
                        if (k < L[l][3]) {
                            if (k < L[l][2]) {
                                L[l][3] = L[l][2];
                                if (k < L[l][1]) {
                                    L[l][2] = L[l][1];
                                    if (k < L[l][0]) { L[l][1] = L[l][0]; L[l][0] = k; }
                                    else             { L[l][1] = k; }
                                } else { L[l][2] = k; }
                            } else { L[l][3] = k; }
                        }
                    }
                }
            }
#pragma unroll
            for (int a = 0; a < 2; ++a)
#pragma unroll
                for (int j = 0; j < 8; ++j)
#pragma unroll
                    for (int k = 0; k < 4; ++k) acc[a][j][k] = 0.0f;
        }
    }

    // ---- dump 32 keys per row ----
#pragma unroll
    for (int l = 0; l < 4; ++l) {
        const int mti = l >> 1, hf = l & 1;
        int rloc = (mw << 5) + (mti << 4) + (hf << 3) + (lane >> 2);
        size_t r = (size_t)g * B_ + (mt0 << 7) + rloc;
        int s8 = (nw << 2) | (lane & 3);
#pragma unroll
        for (int s = 0; s < 4; ++s)
            g_cand[r * 32 + s8 * 4 + s] = L[l][s];
    }
}

// ==================== phase 2: exact fp32 rescore + gather + loss (proven) ====================
#define EPS_RESCORE 0.03f

__global__ void rescore_gather_kernel(const float* __restrict__ feats,
                                      const float* __restrict__ cb,
                                      float* __restrict__ out_q,
                                      float* __restrict__ out_idx_f) {
    __shared__ double bs[8];
    const int g = blockIdx.y, w = threadIdx.x >> 5, lane = threadIdx.x & 31;
    const size_t row = (size_t)g * B_ + ((size_t)blockIdx.x << 3) + w;

    uint32_t key = g_cand[row * 32 + lane];
    int   ci = (int)(key & 1023u);
    float cv = unkey(key);

    uint32_t kmin = key;
#pragma unroll
    for (int off = 16; off; off >>= 1)
        kmin = min(kmin, __shfl_xor_sync(0xffffffffu, kmin, off));
    float vminf = unkey(kmin);
    unsigned mask = __ballot_sync(0xffffffffu, cv <= vminf + EPS_RESCORE);

    const float4* f4 = (const float4*)(feats + row * D_);
    int bestI;
    if (__popc(mask) == 1) {
        bestI = (int)(kmin & 1023u);
    } else {
        float4 fa = f4[lane * 2], fb = f4[lane * 2 + 1];
        const float rn = g_rownorm[row];
        float bestV = 3.4e38f;
        bestI = 0x7fffffff;
        unsigned m = mask;
        while (m) {
            int j = __ffs(m) - 1;
            m &= m - 1;
            int idx = __shfl_sync(0xffffffffu, ci, j);
            const float4* c4 = (const float4*)(cb + ((size_t)g * K_ + idx) * D_);
            float4 ca = c4[lane * 2], cbv = c4[lane * 2 + 1];
            float p = fa.x*ca.x + fa.y*ca.y + fa.z*ca.z + fa.w*ca.w
                    + fb.x*cbv.x + fb.y*cbv.y + fb.z*cbv.z + fb.w*cbv.w;
#pragma unroll
            for (int off = 16; off; off >>= 1) p += __shfl_xor_sync(0xffffffffu, p, off);
            float cn = g_cbnorm[(size_t)g * K_ + idx];
            float d2 = (rn + cn) - 2.0f * p;       // reference rounding structure (exact)
            if (d2 < bestV || (d2 == bestV && idx < bestI)) { bestV = d2; bestI = idx; }
        }
    }

    const float4* q4 = (const float4*)(cb + ((size_t)g * K_ + bestI) * D_);
    float4* o4 = (float4*)(out_q + row * D_);
    float sl = 0.0f;
#pragma unroll
    for (int it = 0; it < 2; ++it) {
        int p = lane + (it << 5);
        float4 f = f4[p], q = q4[p], o;
        float t;
        t = q.x - f.x; o.x = f.x + t; sl += t * t;
        t = q.y - f.y; o.y = f.y + t; sl += t * t;
        t = q.z - f.z; o.z = f.z + t; sl += t * t;
        t = q.w - f.w; o.w = f.w + t; sl += t * t;
        o4[p] = o;
    }
    double s = (double)sl;
#pragma unroll
    for (int off = 16; off; off >>= 1) s += __shfl_down_sync(0xffffffffu, s, off);
    if (!lane) {
        bs[w] = s;
        out_idx_f[row] = (float)bestI;
    }
    __syncthreads();
    if (!threadIdx.x) {
        double tot = 0.0;
#pragma unroll
        for (int i = 0; i < 8; i++) tot += bs[i];
        g_part[(size_t)g * (B_ / 8) + blockIdx.x] = tot;
    }
}

// ==================== loss finalize: per-group blocks + combine ====================
// Same per-group arithmetic and summation order as the proven single-block
// finalize; all indices statically in-bounds.
__global__ void finalize1_kernel() {
    __shared__ double sh[256];
    const int g = blockIdx.x;           // 0..G_-1
    int tid = threadIdx.x;
    double s = 0.0;
    for (int i = tid; i < B_ / 8; i += 256) s += g_part[(size_t)g * (B_ / 8) + i];
    sh[tid] = s;
    __syncthreads();
    for (int st = 128; st; st >>= 1) {
        if (tid < st) sh[tid] += sh[tid + st];
        __syncthreads();
    }
    if (!tid) g_gm[g] = (float)(sh[0] / (double)((size_t)B_ * D_));
}
__global__ void finalize2_kernel(float* __restrict__ out_loss) {
    if (threadIdx.x == 0) {
        const float commit[G_] = {0.5f, 0.5f, 0.4f, 0.4f, 0.4f,
                                  0.4f, 0.8f, 0.8f, 0.8f, 0.8f};
        float total = 0.0f;
        for (int g = 0; g < G_; ++g) {
            float e = g_gm[g];
            total += e + commit[g] * e;   // same order/expression as proven finalize
        }
        *out_loss = total;
    }
}

// ==================== launch ====================
extern "C" void kernel_launch(void* const* d_in, const int* in_sizes, int n_in,
                              void* d_out, int out_size) {
    (void)in_sizes; (void)n_in; (void)out_size;
    const float* feats = (const float*)d_in[0];
    const float* cb    = (const float*)d_in[1];
    float* out      = (float*)d_out;
    float* out_q    = out;
    float* out_loss = out + (size_t)G_ * B_ * D_;
    float* out_idx  = out_loss + 1;

    cudaFuncSetAttribute(vq_f16_kernel, cudaFuncAttributeMaxDynamicSharedMemorySize,
                         SMEM_GEMM);

    dim3 pc(8, G_);
    prep_cb_kernel<<<pc, 256>>>(cb);             // B image + fused cbnorm (R14-proven)

    dim3 pf(B_ / 128, G_);
    prep_feats_kernel<<<pf, 256>>>(feats);       // A image + fused rownorm (R12-proven)

    dim3 mg(B_ / 128, G_);
    vq_f16_kernel<<<mg, 256, SMEM_GEMM>>>();     // byte-identical R12 GEMM core

    dim3 gg(B_ / 8, G_);
    rescore_gather_kernel<<<gg, 256>>>(feats, cb, out_q, out_idx);

    finalize1_kernel<<<G_, 256>>>();
    finalize2_kernel<<<1, 32>>>(out_loss);
}

// round 17
// speedup vs baseline: 1.2019x; 1.0277x over previous
#include <cuda_runtime.h>
#include <cuda_fp16.h>
#include <cstdint>

#define G_ 10
#define B_ 32768
#define K_ 1024
#define D_ 256

// ==================== static device scratch ====================
__device__ float    g_rownorm[G_ * B_];
__device__ float    g_cbnorm [G_ * K_];
__device__ double   g_part   [G_ * (B_ / 8)];
__device__ float    g_gm     [G_];
__device__ uint32_t g_cand   [(size_t)G_ * B_ * 32];               // packed keys
// FP16 fragment-image copies
__device__ __half   g_featsH[(size_t)G_ * (B_ / 128) * 8 * 4096];   // 168 MB
__device__ __half   g_cbH   [(size_t)G_ * 8 * 8 * 4096];            // 5.25 MB

// ==================== helpers ====================
__device__ __forceinline__ void mma_f16(float* c, const uint32_t* a, const uint32_t* b) {
    asm volatile(
        "mma.sync.aligned.m16n8k16.row.col.f32.f16.f16.f32 "
        "{%0,%1,%2,%3}, {%4,%5,%6,%7}, {%8,%9}, {%0,%1,%2,%3};"
        : "+f"(c[0]), "+f"(c[1]), "+f"(c[2]), "+f"(c[3])
        : "r"(a[0]), "r"(a[1]), "r"(a[2]), "r"(a[3]), "r"(b[0]), "r"(b[1]));
}
__device__ __forceinline__ uint32_t smem_u32(const void* p) {
    uint32_t a;
    asm("{ .reg .u64 t; cvta.to.shared.u64 t, %1; cvt.u32.u64 %0, t; }" : "=r"(a) : "l"(p));
    return a;
}
__device__ __forceinline__ void cp16(uint32_t dst, const void* src) {
    asm volatile("cp.async.cg.shared.global [%0], [%1], 16;" :: "r"(dst), "l"(src));
}
#define CP_COMMIT() asm volatile("cp.async.commit_group;" ::: "memory")
#define CP_WAIT1()  asm volatile("cp.async.wait_group 1;" ::: "memory")

// Order-preserving key on UNBIASED scores — BIT-IDENTICAL mapping to the
// R9-R16-proven version, branchless form (SHF+LOP3 instead of ISETP+SEL):
//   positive b: mask=0        -> u = b ^ 0x80000000 = b | 0x80000000  (same)
//   negative b: mask=0xFFFFFFFF -> u = b ^ 0xFFFFFFFF = ~b            (same)
__device__ __forceinline__ uint32_t fkey(float v, int idx) {
    uint32_t b = __float_as_uint(v);
    uint32_t u = b ^ ((uint32_t)(((int32_t)b) >> 31) | 0x80000000u);
    return (u & 0xFFFFFC00u) | (uint32_t)idx;
}
__device__ __forceinline__ float unkey(uint32_t key) {
    uint32_t u = key & 0xFFFFFC00u;
    uint32_t b = (u & 0x80000000u) ? (u ^ 0x80000000u) : ~u;
    return __uint_as_float(b);
}

// ==================== merged prep: cb blocks then feats blocks ====================
// blockIdx.x in [0,8): prep_cb body (R14-proven, nt0 = blockIdx.x)
// blockIdx.x in [8,8+256): prep_feats body (R12-proven, mt0 = blockIdx.x - 8)
__global__ void prep_all_kernel(const float* __restrict__ feats,
                                const float* __restrict__ cb) {
    __shared__ __align__(16) __half img[4096];
    const int tid = threadIdx.x;
    const int g = blockIdx.y;

    if (blockIdx.x < 8) {
        // ---------- prep_cb body (verbatim R14-proven) ----------
        const int nt0 = blockIdx.x;
        const int n = tid >> 1, ks = tid & 1;
        const int pP = n >> 4, qQ = (n >> 3) & 1;
        const float* Cb = cb + ((size_t)g * K_ + (nt0 << 7)) * D_;
        const float* C = Cb + (size_t)n * D_;
        __half* dst = g_cbH + (size_t)(g * 8 + nt0) * 8 * 4096;
        for (int c = 0; c < 8; ++c) {
            const float4* p = (const float4*)(C + (c << 5) + (ks << 4));
            float4 t0 = p[0], t1 = p[1], t2 = p[2], t3 = p[3];
            float v[16] = {t0.x,t0.y,t0.z,t0.w, t1.x,t1.y,t1.z,t1.w,
                           t2.x,t2.y,t2.z,t2.w, t3.x,t3.y,t3.z,t3.w};
#pragma unroll
            for (int jj = 0; jj < 16; jj += 2) {
                int lane = ((n & 7) << 2) | ((jj & 7) >> 1);
                int reg  = jj >> 3;
                int off  = ks * 2048 + pP * 256 + lane * 8 + qQ * 4 + reg * 2;
                *(__half2*)(img + off) = __floats2half2_rn(v[jj], v[jj + 1]);
            }
            __syncthreads();
            float4* o = (float4*)(dst + (size_t)c * 4096 + tid * 16);
            const float4* s = (const float4*)(img + tid * 16);
            o[0] = s[0]; o[1] = s[1];
            __syncthreads();
        }
        const int wid = tid >> 5, lane = tid & 31;
        for (int rr = 0; rr < 16; ++rr) {
            int row = (wid << 4) + rr;
            const float4* rp = (const float4*)(Cb + (size_t)row * D_);
            float4 a = rp[lane], b = rp[lane + 32];
            float s = a.x*a.x + a.y*a.y + a.z*a.z + a.w*a.w
                    + b.x*b.x + b.y*b.y + b.z*b.z + b.w*b.w;
#pragma unroll
            for (int off = 16; off; off >>= 1) s += __shfl_down_sync(0xffffffffu, s, off);
            if (!lane) g_cbnorm[(size_t)g * K_ + (nt0 << 7) + row] = s;
        }
    } else {
        // ---------- prep_feats body (verbatim R12-proven) ----------
        const int mt0 = blockIdx.x - 8;
        const int srow = tid >> 1, ks = tid & 1;
        const int r = srow & 15, mt = srow >> 4;
        const float* Fb = feats + ((size_t)g * B_ + (mt0 << 7)) * D_;
        const float* F = Fb + (size_t)srow * D_;
        __half* dst = g_featsH + (size_t)(g * (B_ / 128) + mt0) * 8 * 4096;
        for (int c = 0; c < 8; ++c) {
            const float4* p = (const float4*)(F + (c << 5) + (ks << 4));
            float4 t0 = p[0], t1 = p[1], t2 = p[2], t3 = p[3];
            float v[16] = {t0.x,t0.y,t0.z,t0.w, t1.x,t1.y,t1.z,t1.w,
                           t2.x,t2.y,t2.z,t2.w, t3.x,t3.y,t3.z,t3.w};
#pragma unroll
            for (int jj = 0; jj < 16; jj += 2) {
                int lane = ((r & 7) << 2) | ((jj & 7) >> 1);
                int reg  = ((jj >> 3) << 1) | (r >> 3);
                int off  = ks * 2048 + mt * 256 + lane * 8 + reg * 2;
                *(__half2*)(img + off) = __floats2half2_rn(v[jj], v[jj + 1]);
            }
            __syncthreads();
            float4* o = (float4*)(dst + (size_t)c * 4096 + tid * 16);
            const float4* s = (const float4*)(img + tid * 16);
            o[0] = s[0]; o[1] = s[1];
            __syncthreads();
        }
        const int wid = tid >> 5, lane = tid & 31;
        for (int rr = 0; rr < 16; ++rr) {
            int row = (wid << 4) + rr;
            const float4* rp = (const float4*)(Fb + (size_t)row * D_);
            float4 a = rp[lane], b = rp[lane + 32];
            float s = a.x*a.x + a.y*a.y + a.z*a.z + a.w*a.w
                    + b.x*b.x + b.y*b.y + b.z*b.z + b.w*b.w;
#pragma unroll
            for (int off = 16; off; off >>= 1) s += __shfl_down_sync(0xffffffffu, s, off);
            if (!lane) g_rownorm[(size_t)g * B_ + (mt0 << 7) + row] = s;
        }
    }
}

// ==================== phase 1: fp16 GEMM (R12/R16 core; fkey swap only) ====================
#define SMEM_GEMM (112 * 1024)

__global__ void __launch_bounds__(256, 2)
vq_f16_kernel() {
    extern __shared__ __half smh[];
    const uint32_t sb = smem_u32(smh);
    const int tid  = threadIdx.x;
    const int wid  = tid >> 5;
    const int lane = tid & 31;
    const int g    = blockIdx.y;
    const int mt0  = blockIdx.x;
    const int mw   = wid >> 1;
    const int nw   = wid & 1;

    const __half* srcA0 = g_featsH + (size_t)(g * (B_ / 128) + mt0) * 8 * 4096;
    const __half* srcB0 = g_cbH + (size_t)g * 8 * 8 * 4096;

    uint32_t L[4][4];
#pragma unroll
    for (int l = 0; l < 4; ++l)
#pragma unroll
        for (int s = 0; s < 4; ++s) L[l][s] = 0xFFFFFFFFu;

    float acc[2][8][4];
#pragma unroll
    for (int i = 0; i < 2; ++i)
#pragma unroll
        for (int j = 0; j < 8; ++j)
#pragma unroll
            for (int k = 0; k < 4; ++k) acc[i][j][k] = 0.0f;

    // prologue: resident A (1 group), then B stages 0,1 (1 group each)
#pragma unroll
    for (int c = 0; c < 8; ++c) {
        uint32_t d = sb + c * 8192 + tid * 32;
        const __half* sa = srcA0 + (size_t)c * 4096 + tid * 16;
        cp16(d, sa); cp16(d + 16, sa + 8);
    }
    CP_COMMIT();
#pragma unroll
    for (int s = 0; s < 2; ++s) {
        uint32_t d = sb + 65536 + s * 16384 + tid * 64;
        const __half* sbp = srcB0 + (size_t)s * 8192 + tid * 32;
        cp16(d, sbp); cp16(d + 16, sbp + 8);
        cp16(d + 32, sbp + 16); cp16(d + 48, sbp + 24);
        CP_COMMIT();
    }

    for (int i = 0; i < 32; ++i) {
        CP_WAIT1();
        __syncthreads();
        const __half* bufBs = smh + 32768 + (i % 3) * 8192;

        // ---- MMA on two 32-d sub-chunks (R11/R12-validated reads) ----
#pragma unroll
        for (int u = 0; u < 2; ++u) {
            const __half* bufA = smh + (((i << 1) + u) & 7) * 4096;
            const __half* bufB = bufBs + (u << 12);
#pragma unroll
            for (int ks = 0; ks < 2; ++ks) {
                uint32_t aF[2][4];
#pragma unroll
                for (int mti = 0; mti < 2; ++mti) {
                    uint4 t = *(const uint4*)(bufA + ks * 2048 + ((mw << 1) + mti) * 256 + lane * 8);
                    aF[mti][0] = t.x; aF[mti][1] = t.y; aF[mti][2] = t.z; aF[mti][3] = t.w;
                }
#pragma unroll
                for (int pp = 0; pp < 4; ++pp) {
                    uint4 bt = *(const uint4*)(bufB + ks * 2048 + ((nw << 2) + pp) * 256 + lane * 8);
                    uint32_t b0[2] = {bt.x, bt.y};
                    uint32_t b1[2] = {bt.z, bt.w};
                    mma_f16(acc[0][(pp << 1)],     aF[0], b0);
                    mma_f16(acc[1][(pp << 1)],     aF[1], b0);
                    mma_f16(acc[0][(pp << 1) + 1], aF[0], b1);
                    mma_f16(acc[1][(pp << 1) + 1], aF[1], b1);
                }
            }
        }

        // ---- refill B stage i+2 ----
        if (i + 2 < 32) {
            const int s = (i + 2) % 3;
            uint32_t d = sb + 65536 + s * 16384 + tid * 64;
            const __half* sbp = srcB0 + (size_t)(i + 2) * 8192 + tid * 32;
            cp16(d, sbp); cp16(d + 16, sbp + 8);
            cp16(d + 32, sbp + 16); cp16(d + 48, sbp + 24);
        }
        CP_COMMIT();

        // ---- epilogue every 4 iters: per-score top-4 insertion (R12-proven) ----
        if ((i & 3) == 3) {
            const int ntile = i >> 2;
            const float* cnb = g_cbnorm + (size_t)g * K_ + (ntile << 7);
#pragma unroll
            for (int p = 0; p < 4; ++p) {
                int cl0 = (nw << 6) + (p << 4) + ((lane & 3) << 1);
                float2 cnA = __ldg((const float2*)(cnb + cl0));
                float2 cnB = __ldg((const float2*)(cnb + cl0 + 8));
                int gi0 = (ntile << 7) + cl0;
                int gi1 = gi0 + 8;
#pragma unroll
                for (int l = 0; l < 4; ++l) {
                    const int mti = l >> 1, hf = l & 1;
                    float sc[4];
                    int   gi[4];
                    sc[0] = cnA.x - 2.0f * acc[mti][(p << 1)][(hf << 1)];     gi[0] = gi0;
                    sc[1] = cnA.y - 2.0f * acc[mti][(p << 1)][(hf << 1) + 1]; gi[1] = gi0 + 1;
                    sc[2] = cnB.x - 2.0f * acc[mti][(p << 1) + 1][(hf << 1)];     gi[2] = gi1;
                    sc[3] = cnB.y - 2.0f * acc[mti][(p << 1) + 1][(hf << 1) + 1]; gi[3] = gi1 + 1;
#pragma unroll
                    for (int q = 0; q < 4; ++q) {
                        uint32_t k = fkey(sc[q], gi[q]);
                        if (k < L[l][3]) {
                            if (k < L[l][2]) {
                                L[l][3] = L[l][2];
                                if (k < L[l][1]) {
                                    L[l][2] = L[l][1];
                                    if (k < L[l][0]) { L[l][1] = L[l][0]; L[l][0] = k; }
                                    else             { L[l][1] = k; }
                                } else { L[l][2] = k; }
                            } else { L[l][3] = k; }
                        }
                    }
                }
            }
#pragma unroll
            for (int a = 0; a < 2; ++a)
#pragma unroll
                for (int j = 0; j < 8; ++j)
#pragma unroll
                    for (int k = 0; k < 4; ++k) acc[a][j][k] = 0.0f;
        }
    }

    // ---- dump 32 keys per row ----
#pragma unroll
    for (int l = 0; l < 4; ++l) {
        const int mti = l >> 1, hf = l & 1;
        int rloc = (mw << 5) + (mti << 4) + (hf << 3) + (lane >> 2);
        size_t r = (size_t)g * B_ + (mt0 << 7) + rloc;
        int s8 = (nw << 2) | (lane & 3);
#pragma unroll
        for (int s = 0; s < 4; ++s)
            g_cand[r * 32 + s8 * 4 + s] = L[l][s];
    }
}

// ==================== phase 2: exact fp32 rescore + gather + loss ====================
// Proven logic; changes here are hint/scheduling only: feats loads hoisted
// above the key-reduction chain, last-use loads via __ldcs, streaming stores.
#define EPS_RESCORE 0.03f

__global__ void rescore_gather_kernel(const float* __restrict__ feats,
                                      const float* __restrict__ cb,
                                      float* __restrict__ out_q,
                                      float* __restrict__ out_idx_f) {
    __shared__ double bs[8];
    const int g = blockIdx.y, w = threadIdx.x >> 5, lane = threadIdx.x & 31;
    const size_t row = (size_t)g * B_ + ((size_t)blockIdx.x << 3) + w;

    const float4* f4 = (const float4*)(feats + row * D_);
    // hoisted: overlap these LDGs with the dependent key-reduce chain below
    float4 fA = __ldcs(f4 + lane * 2);
    float4 fB = __ldcs(f4 + lane * 2 + 1);

    uint32_t key = g_cand[row * 32 + lane];
    int   ci = (int)(key & 1023u);
    float cv = unkey(key);

    uint32_t kmin = key;
#pragma unroll
    for (int off = 16; off; off >>= 1)
        kmin = min(kmin, __shfl_xor_sync(0xffffffffu, kmin, off));
    float vminf = unkey(kmin);
    unsigned mask = __ballot_sync(0xffffffffu, cv <= vminf + EPS_RESCORE);

    int bestI;
    if (__popc(mask) == 1) {
        bestI = (int)(kmin & 1023u);
    } else {
        const float rn = g_rownorm[row];
        float bestV = 3.4e38f;
        bestI = 0x7fffffff;
        unsigned m = mask;
        while (m) {
            int j = __ffs(m) - 1;
            m &= m - 1;
            int idx = __shfl_sync(0xffffffffu, ci, j);
            const float4* c4 = (const float4*)(cb + ((size_t)g * K_ + idx) * D_);
            float4 ca = c4[lane * 2], cbv = c4[lane * 2 + 1];
            float p = fA.x*ca.x + fA.y*ca.y + fA.z*ca.z + fA.w*ca.w
                    + fB.x*cbv.x + fB.y*cbv.y + fB.z*cbv.z + fB.w*cbv.w;
#pragma unroll
            for (int off = 16; off; off >>= 1) p += __shfl_xor_sync(0xffffffffu, p, off);
            float cn = g_cbnorm[(size_t)g * K_ + idx];
            float d2 = (rn + cn) - 2.0f * p;       // reference rounding structure (exact)
            if (d2 < bestV || (d2 == bestV && idx < bestI)) { bestV = d2; bestI = idx; }
        }
    }

    const float4* q4 = (const float4*)(cb + ((size_t)g * K_ + bestI) * D_);
    float4* o4 = (float4*)(out_q + row * D_);
    float sl = 0.0f;
    // element pass 1: reuse the hoisted fA/fB (p = lane*2, lane*2+1)
    {
        float4 q = q4[lane * 2], o;
        float t;
        t = q.x - fA.x; o.x = fA.x + t; sl += t * t;
        t = q.y - fA.y; o.y = fA.y + t; sl += t * t;
        t = q.z - fA.z; o.z = fA.z + t; sl += t * t;
        t = q.w - fA.w; o.w = fA.w + t; sl += t * t;
        __stcs(o4 + lane * 2, o);
        q = q4[lane * 2 + 1];
        t = q.x - fB.x; o.x = fB.x + t; sl += t * t;
        t = q.y - fB.y; o.y = fB.y + t; sl += t * t;
        t = q.z - fB.z; o.z = fB.z + t; sl += t * t;
        t = q.w - fB.w; o.w = fB.w + t; sl += t * t;
        __stcs(o4 + lane * 2 + 1, o);
    }
    double s = (double)sl;
#pragma unroll
    for (int off = 16; off; off >>= 1) s += __shfl_down_sync(0xffffffffu, s, off);
    if (!lane) {
        bs[w] = s;
        out_idx_f[row] = (float)bestI;
    }
    __syncthreads();
    if (!threadIdx.x) {
        double tot = 0.0;
#pragma unroll
        for (int i = 0; i < 8; i++) tot += bs[i];
        g_part[(size_t)g * (B_ / 8) + blockIdx.x] = tot;
    }
}

// ==================== loss finalize: per-group blocks + combine (R16-proven) ====================
__global__ void finalize1_kernel() {
    __shared__ double sh[256];
    const int g = blockIdx.x;
    int tid = threadIdx.x;
    double s = 0.0;
    for (int i = tid; i < B_ / 8; i += 256) s += g_part[(size_t)g * (B_ / 8) + i];
    sh[tid] = s;
    __syncthreads();
    for (int st = 128; st; st >>= 1) {
        if (tid < st) sh[tid] += sh[tid + st];
        __syncthreads();
    }
    if (!tid) g_gm[g] = (float)(sh[0] / (double)((size_t)B_ * D_));
}
__global__ void finalize2_kernel(float* __restrict__ out_loss) {
    if (threadIdx.x == 0) {
        const float commit[G_] = {0.5f, 0.5f, 0.4f, 0.4f, 0.4f,
                                  0.4f, 0.8f, 0.8f, 0.8f, 0.8f};
        float total = 0.0f;
        for (int g = 0; g < G_; ++g) {
            float e = g_gm[g];
            total += e + commit[g] * e;
        }
        *out_loss = total;
    }
}

// ==================== launch ====================
extern "C" void kernel_launch(void* const* d_in, const int* in_sizes, int n_in,
                              void* d_out, int out_size) {
    (void)in_sizes; (void)n_in; (void)out_size;
    const float* feats = (const float*)d_in[0];
    const float* cb    = (const float*)d_in[1];
    float* out      = (float*)d_out;
    float* out_q    = out;
    float* out_loss = out + (size_t)G_ * B_ * D_;
    float* out_idx  = out_loss + 1;

    cudaFuncSetAttribute(vq_f16_kernel, cudaFuncAttributeMaxDynamicSharedMemorySize,
                         SMEM_GEMM);

    dim3 pa(8 + B_ / 128, G_);
    prep_all_kernel<<<pa, 256>>>(feats, cb);     // cb blocks [0,8) + feats blocks [8,264)

    dim3 mg(B_ / 128, G_);
    vq_f16_kernel<<<mg, 256, SMEM_GEMM>>>();

    dim3 gg(B_ / 8, G_);
    rescore_gather_kernel<<<gg, 256>>>(feats, cb, out_q, out_idx);

    finalize1_kernel<<<G_, 256>>>();
    finalize2_kernel<<<1, 32>>>(out_loss);
}